// round 15
// baseline (speedup 1.0000x reference)
#include <cuda_runtime.h>
#include <cuda_fp16.h>
#include <cstdint>

#define N_NODES 100000
#define N_EDGES 1600000
#define D_FEAT  128
#define N_POOL  25000
#define D4      (D_FEAT / 4)          // 32 float4 per fp32 row
#define N4      (N_NODES * D4)        // 3.2M float4 in x
#define SCAN_B  1024
#define NBLK    ((N_NODES + SCAN_B - 1) / SCAN_B)   // 98

// ---- scratch (__device__ globals; zero-initialized at load) ---------------
__device__ __half g_xh[(size_t)N_NODES * D_FEAT]; // fp16 copy of x  (hop-1 gather)
__device__ __half g_Yh[(size_t)N_NODES * D_FEAT]; // fp16 hop-1 out  (hop-2 gather)
__device__ int    g_cnt[N_NODES];                 // histogram (self-cleared by scan)
__device__ int    g_off[N_NODES + 1];             // within-tile excl offsets (+sentinel)
__device__ int    g_bsum[NBLK];                   // exclusive tile prefixes
__device__ int    g_done;                         // scan completion counter (self-reset)
__device__ int    g_rank[N_EDGES];                // edge rank within its dst bucket
__device__ int2   g_epack[N_EDGES];               // (src*32, weight-bits) sorted by dst

// ---------------------------------------------------------------------------
// Fused histogram + rank capture + fp16 convert.
// The atomicAdd RETURN VALUE is each edge's rank within its dst bucket —
// persisting it makes the reorder pass atomic-free.
// ---------------------------------------------------------------------------
__global__ void hist_convert_kernel(const int4* __restrict__ dst4,
                                    const float4* __restrict__ x4) {
    int i = blockIdx.x * blockDim.x + threadIdx.x;
    if (i < N_EDGES / 4) {
        int4 d = __ldg(&dst4[i]);
        int4 r;
        r.x = atomicAdd(&g_cnt[d.x], 1);
        r.y = atomicAdd(&g_cnt[d.y], 1);
        r.z = atomicAdd(&g_cnt[d.z], 1);
        r.w = atomicAdd(&g_cnt[d.w], 1);
        reinterpret_cast<int4*>(g_rank)[i] = r;    // coalesced 16B store
    }
    if (i < N4) {
        float4 v = __ldg(&x4[i]);
        __half2 h01 = __floats2half2_rn(v.x, v.y);
        __half2 h23 = __floats2half2_rn(v.z, v.w);
        uint2 p;
        p.x = *reinterpret_cast<unsigned int*>(&h01);
        p.y = *reinterpret_cast<unsigned int*>(&h23);
        reinterpret_cast<uint2*>(g_xh)[i] = p;
    }
}

// ---------------------------------------------------------------------------
// Fused scan: within-tile offsets + lazy tile prefixes; self-cleans g_cnt and
// g_done for graph replay. Global offset of n = g_off[n] + g_bsum[n >> 10].
// ---------------------------------------------------------------------------
__global__ void __launch_bounds__(SCAN_B) scan_fused_kernel() {
    __shared__ int wsum[32];
    __shared__ int is_last;
    int i = blockIdx.x * SCAN_B + threadIdx.x;
    int v = (i < N_NODES) ? g_cnt[i] : 0;
    if (i < N_NODES) g_cnt[i] = 0;                 // self-clear for next replay
    int lane = threadIdx.x & 31, w = threadIdx.x >> 5;
    int s = v;
    #pragma unroll
    for (int d = 1; d < 32; d <<= 1) {
        int u = __shfl_up_sync(0xffffffffu, s, d);
        if (lane >= d) s += u;
    }
    if (lane == 31) wsum[w] = s;
    __syncthreads();
    if (w == 0) {
        int ws = wsum[lane];
        #pragma unroll
        for (int d = 1; d < 32; d <<= 1) {
            int u = __shfl_up_sync(0xffffffffu, ws, d);
            if (lane >= d) ws += u;
        }
        wsum[lane] = ws;
    }
    __syncthreads();
    int incl = s + (w > 0 ? wsum[w - 1] : 0);
    if (i <= N_NODES) g_off[i] = incl - v;         // within-tile exclusive (+sentinel)
    if (threadIdx.x == SCAN_B - 1) g_bsum[blockIdx.x] = incl;  // tile total

    __threadfence();
    if (threadIdx.x == 0)
        is_last = (atomicAdd(&g_done, 1) == gridDim.x - 1);
    __syncthreads();
    if (is_last) {
        __shared__ int wsum2[4];
        int t = threadIdx.x;
        int bv = 0;
        if (t < NBLK) {
            const volatile int* bs = g_bsum;
            bv = bs[t];
        }
        if (t < 128) {
            int s2 = bv;
            #pragma unroll
            for (int d = 1; d < 32; d <<= 1) {
                int u = __shfl_up_sync(0xffffffffu, s2, d);
                if (lane >= d) s2 += u;
            }
            if (lane == 31) wsum2[w] = s2;
        }
        __syncthreads();
        if (t < 32) {
            int ws = (lane < 4) ? wsum2[lane] : 0;
            #pragma unroll
            for (int d = 1; d < 4; d <<= 1) {
                int u = __shfl_up_sync(0xffffffffu, ws, d);
                if (lane >= d) ws += u;
            }
            if (lane < 4) wsum2[lane] = ws;
        }
        __syncthreads();
        if (t < NBLK) {
            int s2 = bv;
            #pragma unroll
            for (int d = 1; d < 32; d <<= 1) {
                int u = __shfl_up_sync(0xffffffffu, s2, d);
                if (lane >= d) s2 += u;
            }
            int incl2 = s2 + (w > 0 ? wsum2[w - 1] : 0);
            g_bsum[t] = incl2 - bv;                // exclusive tile prefix
        }
        if (threadIdx.x == 0) g_done = 0;          // self-reset for next replay
    }
}

// ---------------------------------------------------------------------------
// Reorder, ATOMIC-FREE: pos = off[dst] + bsum[tile] + rank (captured in hist).
// 2 edges per thread, vectorized input loads. Record = (src*32, weight-bits).
// ---------------------------------------------------------------------------
__global__ void reorder_kernel(const int2* __restrict__ src2,
                               const int2* __restrict__ dst2,
                               const float2* __restrict__ ea2) {
    int i = blockIdx.x * blockDim.x + threadIdx.x;
    if (i < N_EDGES / 2) {
        int2   s = __ldg(&src2[i]);
        int2   d = __ldg(&dst2[i]);
        float2 w = __ldg(&ea2[i]);
        int2   r = __ldg(&reinterpret_cast<const int2*>(g_rank)[i]);
        int p0 = __ldg(&g_off[d.x]) + __ldg(&g_bsum[d.x >> 10]) + r.x;
        g_epack[p0] = make_int2(s.x << 5, __float_as_int(w.x));
        int p1 = __ldg(&g_off[d.y]) + __ldg(&g_bsum[d.y >> 10]) + r.y;
        g_epack[p1] = make_int2(s.y << 5, __float_as_int(w.y));
    }
}

// ---------------------------------------------------------------------------
// Hop 1 (all nodes): Yh[n] = half( xh[n] + sum_e xh[src_e] * w_e )
// Simple unroll-4 loop — R13 showed pairing kills software pipelining.
// ---------------------------------------------------------------------------
__global__ void __launch_bounds__(256) hop1_kernel()
{
    int n    = (blockIdx.x * blockDim.x + threadIdx.x) >> 5;
    int lane = threadIdx.x & 31;
    if (n >= N_NODES) return;

    const uint2* xh2 = reinterpret_cast<const uint2*>(g_xh);

    // residual from fp16 x row
    uint2 r = __ldg(&xh2[(size_t)n * D4 + lane]);
    __half2 r01 = *reinterpret_cast<__half2*>(&r.x);
    __half2 r23 = *reinterpret_cast<__half2*>(&r.y);
    float2 q01 = __half22float2(r01);
    float2 q23 = __half22float2(r23);
    float4 acc = make_float4(q01.x, q01.y, q23.x, q23.y);

    int s0 = __ldg(&g_off[n])     + __ldg(&g_bsum[n >> 10]);
    int e0 = __ldg(&g_off[n + 1]) + __ldg(&g_bsum[(n + 1) >> 10]);

    #pragma unroll 4
    for (int j = s0; j < e0; ++j) {
        int2 e = __ldg(&g_epack[j]);               // uniform broadcast
        float w = __int_as_float(e.y);
        uint2 h = __ldg(&xh2[(size_t)(unsigned)e.x + lane]);  // fp16 row
        __half2 h01 = *reinterpret_cast<__half2*>(&h.x);
        __half2 h23 = *reinterpret_cast<__half2*>(&h.y);
        float2 f01 = __half22float2(h01);
        float2 f23 = __half22float2(h23);
        acc.x += f01.x * w;
        acc.y += f01.y * w;
        acc.z += f23.x * w;
        acc.w += f23.y * w;
    }
    __half2 o01 = __floats2half2_rn(acc.x, acc.y);
    __half2 o23 = __floats2half2_rn(acc.z, acc.w);
    uint2 p;
    p.x = *reinterpret_cast<unsigned int*>(&o01);
    p.y = *reinterpret_cast<unsigned int*>(&o23);
    reinterpret_cast<uint2*>(g_Yh)[(size_t)n * D4 + lane] = p;
}

// ---------------------------------------------------------------------------
// Hop 2 fused with selection gather: one warp per OUTPUT row, fp16 gathers,
// fp32 accumulate, fp32 output.
//   out[i] = Yh[sel[i]] + sum_{e in CSR(sel[i])} Yh[src_e] * w_e
// ---------------------------------------------------------------------------
__global__ void __launch_bounds__(256) hop2_direct_kernel(
    const int* __restrict__ sel,
    float4* __restrict__ out4)
{
    int row  = (blockIdx.x * blockDim.x + threadIdx.x) >> 5;
    int lane = threadIdx.x & 31;
    if (row >= N_POOL) return;

    int n = __ldg(sel + row);
    const uint2* yh2 = reinterpret_cast<const uint2*>(g_Yh);

    // residual from fp16 Y row
    uint2 r = __ldg(&yh2[(size_t)n * D4 + lane]);
    __half2 r01 = *reinterpret_cast<__half2*>(&r.x);
    __half2 r23 = *reinterpret_cast<__half2*>(&r.y);
    float2 q01 = __half22float2(r01);
    float2 q23 = __half22float2(r23);
    float4 acc = make_float4(q01.x, q01.y, q23.x, q23.y);

    int s0 = __ldg(&g_off[n])     + __ldg(&g_bsum[n >> 10]);
    int e0 = __ldg(&g_off[n + 1]) + __ldg(&g_bsum[(n + 1) >> 10]);

    #pragma unroll 4
    for (int j = s0; j < e0; ++j) {
        int2 e = __ldg(&g_epack[j]);               // uniform broadcast
        float w = __int_as_float(e.y);
        uint2 h = __ldg(&yh2[(size_t)(unsigned)e.x + lane]);
        __half2 h01 = *reinterpret_cast<__half2*>(&h.x);
        __half2 h23 = *reinterpret_cast<__half2*>(&h.y);
        float2 f01 = __half22float2(h01);
        float2 f23 = __half22float2(h23);
        acc.x += f01.x * w;
        acc.y += f01.y * w;
        acc.z += f23.x * w;
        acc.w += f23.y * w;
    }
    out4[(size_t)row * D4 + lane] = acc;
}

// ---------------------------------------------------------------------------
extern "C" void kernel_launch(void* const* d_in, const int* in_sizes, int n_in,
                              void* d_out, int out_size)
{
    const float* x    = (const float*)d_in[0];   // [N, 128] f32
    const float* ea   = (const float*)d_in[1];   // [E] f32
    const int*   eidx = (const int*)d_in[2];     // [2, E] int32
    const int*   sel  = (const int*)d_in[3];     // [N_pool] int32
    float* out = (float*)d_out;

    const int* src = eidx;            // row 0 (x_j sources)
    const int* dst = eidx + N_EDGES;  // row 1 (aggregation targets)

    const float4* x4 = reinterpret_cast<const float4*>(x);
    const int TB = 256;

    // CSR build: (hist+rank|convert) -> fused scan -> atomic-free reorder
    hist_convert_kernel<<<(N4 + TB - 1) / TB, TB>>>(
        reinterpret_cast<const int4*>(dst), x4);
    scan_fused_kernel<<<NBLK, SCAN_B>>>();
    reorder_kernel<<<(N_EDGES / 2 + TB - 1) / TB, TB>>>(
        reinterpret_cast<const int2*>(src),
        reinterpret_cast<const int2*>(dst),
        reinterpret_cast<const float2*>(ea));

    // hop 1 (all nodes, fp16 gather, fp16 residual, fp16 out)
    hop1_kernel<<<(N_NODES * 32 + TB - 1) / TB, TB>>>();

    // hop 2 fused with output gather: out[i] = (Yh + A@Yh)[sel[i]]
    hop2_direct_kernel<<<(N_POOL * 32 + TB - 1) / TB, TB>>>(
        sel, (float4*)out);
}

// round 17
// speedup vs baseline: 1.0529x; 1.0529x over previous
#include <cuda_runtime.h>
#include <cuda_fp16.h>
#include <cstdint>

#define N_NODES 100000
#define N_EDGES 1600000
#define D_FEAT  128
#define N_POOL  25000
#define D4      (D_FEAT / 4)          // 32 float4 per fp32 row
#define N4      (N_NODES * D4)        // 3.2M float4 in x
#define SCAN_B  1024
#define NBLK    ((N_NODES + SCAN_B - 1) / SCAN_B)   // 98

// ---- scratch (__device__ globals; zero-initialized at load) ---------------
__device__ __half g_xh[(size_t)N_NODES * D_FEAT]; // fp16 copy of x  (hop-1 gather)
__device__ __half g_Yh[(size_t)N_NODES * D_FEAT]; // fp16 hop-1 out  (hop-2 gather)
__device__ int    g_cnt[N_NODES];                 // histogram (self-cleared by scan)
__device__ int    g_off[N_NODES + 1];             // within-tile excl offsets (+sentinel)
__device__ int    g_bsum[NBLK];                   // exclusive tile prefixes
__device__ int    g_done;                         // scan completion counter (self-reset)
__device__ int    g_rank[N_EDGES];                // edge rank within its dst bucket
__device__ int2   g_epack[N_EDGES];               // (src*32, weight-bits) sorted by dst

// ---------------------------------------------------------------------------
// Fused histogram + rank capture + fp16 convert.
// x is dead after conversion -> __ldcs (evict-first) keeps the gather-hot
// arrays (xh/Yh/epack) resident in L2.
// ---------------------------------------------------------------------------
__global__ void hist_convert_kernel(const int4* __restrict__ dst4,
                                    const float4* __restrict__ x4) {
    int i = blockIdx.x * blockDim.x + threadIdx.x;
    if (i < N_EDGES / 4) {
        int4 d = __ldg(&dst4[i]);
        int4 r;
        r.x = atomicAdd(&g_cnt[d.x], 1);
        r.y = atomicAdd(&g_cnt[d.y], 1);
        r.z = atomicAdd(&g_cnt[d.z], 1);
        r.w = atomicAdd(&g_cnt[d.w], 1);
        reinterpret_cast<int4*>(g_rank)[i] = r;    // coalesced 16B store
    }
    if (i < N4) {
        float4 v = __ldcs(&x4[i]);                 // streaming read (dead after)
        __half2 h01 = __floats2half2_rn(v.x, v.y);
        __half2 h23 = __floats2half2_rn(v.z, v.w);
        uint2 p;
        p.x = *reinterpret_cast<unsigned int*>(&h01);
        p.y = *reinterpret_cast<unsigned int*>(&h23);
        reinterpret_cast<uint2*>(g_xh)[i] = p;
    }
}

// ---------------------------------------------------------------------------
// Fused scan: within-tile offsets + lazy tile prefixes; self-cleans g_cnt and
// g_done for graph replay. Global offset of n = g_off[n] + g_bsum[n >> 10].
// (NO inter-block spin — R16's resident-grid barrier deadlocked.)
// ---------------------------------------------------------------------------
__global__ void __launch_bounds__(SCAN_B) scan_fused_kernel() {
    __shared__ int wsum[32];
    __shared__ int is_last;
    int i = blockIdx.x * SCAN_B + threadIdx.x;
    int v = (i < N_NODES) ? g_cnt[i] : 0;
    if (i < N_NODES) g_cnt[i] = 0;                 // self-clear for next replay
    int lane = threadIdx.x & 31, w = threadIdx.x >> 5;
    int s = v;
    #pragma unroll
    for (int d = 1; d < 32; d <<= 1) {
        int u = __shfl_up_sync(0xffffffffu, s, d);
        if (lane >= d) s += u;
    }
    if (lane == 31) wsum[w] = s;
    __syncthreads();
    if (w == 0) {
        int ws = wsum[lane];
        #pragma unroll
        for (int d = 1; d < 32; d <<= 1) {
            int u = __shfl_up_sync(0xffffffffu, ws, d);
            if (lane >= d) ws += u;
        }
        wsum[lane] = ws;
    }
    __syncthreads();
    int incl = s + (w > 0 ? wsum[w - 1] : 0);
    if (i <= N_NODES) g_off[i] = incl - v;         // within-tile exclusive (+sentinel)
    if (threadIdx.x == SCAN_B - 1) g_bsum[blockIdx.x] = incl;  // tile total

    __threadfence();
    if (threadIdx.x == 0)
        is_last = (atomicAdd(&g_done, 1) == gridDim.x - 1);
    __syncthreads();
    if (is_last) {
        __shared__ int wsum2[4];
        int t = threadIdx.x;
        int bv = 0;
        if (t < NBLK) {
            const volatile int* bs = g_bsum;       // other SMs wrote these
            bv = bs[t];
        }
        if (t < 128) {
            int s2 = bv;
            #pragma unroll
            for (int d = 1; d < 32; d <<= 1) {
                int u = __shfl_up_sync(0xffffffffu, s2, d);
                if (lane >= d) s2 += u;
            }
            if (lane == 31) wsum2[w] = s2;
        }
        __syncthreads();
        if (t < 32) {
            int ws = (lane < 4) ? wsum2[lane] : 0;
            #pragma unroll
            for (int d = 1; d < 4; d <<= 1) {
                int u = __shfl_up_sync(0xffffffffu, ws, d);
                if (lane >= d) ws += u;
            }
            if (lane < 4) wsum2[lane] = ws;
        }
        __syncthreads();
        if (t < NBLK) {
            int s2 = bv;
            #pragma unroll
            for (int d = 1; d < 32; d <<= 1) {
                int u = __shfl_up_sync(0xffffffffu, s2, d);
                if (lane >= d) s2 += u;
            }
            int incl2 = s2 + (w > 0 ? wsum2[w - 1] : 0);
            g_bsum[t] = incl2 - bv;                // exclusive tile prefix
        }
        if (threadIdx.x == 0) g_done = 0;          // self-reset for next replay
    }
}

// ---------------------------------------------------------------------------
// Reorder, ATOMIC-FREE: pos = off[dst] + bsum[tile] + rank (captured in hist).
// 2 edges per thread, vectorized input loads. Record = (src*32, weight-bits).
// ---------------------------------------------------------------------------
__global__ void reorder_kernel(const int2* __restrict__ src2,
                               const int2* __restrict__ dst2,
                               const float2* __restrict__ ea2) {
    int i = blockIdx.x * blockDim.x + threadIdx.x;
    if (i < N_EDGES / 2) {
        int2   s = __ldg(&src2[i]);
        int2   d = __ldg(&dst2[i]);
        float2 w = __ldg(&ea2[i]);
        int2   r = __ldg(&reinterpret_cast<const int2*>(g_rank)[i]);
        int p0 = __ldg(&g_off[d.x]) + __ldg(&g_bsum[d.x >> 10]) + r.x;
        g_epack[p0] = make_int2(s.x << 5, __float_as_int(w.x));
        int p1 = __ldg(&g_off[d.y]) + __ldg(&g_bsum[d.y >> 10]) + r.y;
        g_epack[p1] = make_int2(s.y << 5, __float_as_int(w.y));
    }
}

// ---------------------------------------------------------------------------
// Hop 1 (all nodes): Yh[n] = half( xh[n] + sum_e xh[src_e] * w_e )
// Simple unroll-4 loop — frozen (R13 showed restructuring regresses).
// ---------------------------------------------------------------------------
__global__ void __launch_bounds__(256) hop1_kernel()
{
    int n    = (blockIdx.x * blockDim.x + threadIdx.x) >> 5;
    int lane = threadIdx.x & 31;
    if (n >= N_NODES) return;

    const uint2* xh2 = reinterpret_cast<const uint2*>(g_xh);

    // residual from fp16 x row
    uint2 r = __ldg(&xh2[(size_t)n * D4 + lane]);
    __half2 r01 = *reinterpret_cast<__half2*>(&r.x);
    __half2 r23 = *reinterpret_cast<__half2*>(&r.y);
    float2 q01 = __half22float2(r01);
    float2 q23 = __half22float2(r23);
    float4 acc = make_float4(q01.x, q01.y, q23.x, q23.y);

    int s0 = __ldg(&g_off[n])     + __ldg(&g_bsum[n >> 10]);
    int e0 = __ldg(&g_off[n + 1]) + __ldg(&g_bsum[(n + 1) >> 10]);

    #pragma unroll 4
    for (int j = s0; j < e0; ++j) {
        int2 e = __ldg(&g_epack[j]);               // uniform broadcast
        float w = __int_as_float(e.y);
        uint2 h = __ldg(&xh2[(size_t)(unsigned)e.x + lane]);  // fp16 row
        __half2 h01 = *reinterpret_cast<__half2*>(&h.x);
        __half2 h23 = *reinterpret_cast<__half2*>(&h.y);
        float2 f01 = __half22float2(h01);
        float2 f23 = __half22float2(h23);
        acc.x += f01.x * w;
        acc.y += f01.y * w;
        acc.z += f23.x * w;
        acc.w += f23.y * w;
    }
    __half2 o01 = __floats2half2_rn(acc.x, acc.y);
    __half2 o23 = __floats2half2_rn(acc.z, acc.w);
    uint2 p;
    p.x = *reinterpret_cast<unsigned int*>(&o01);
    p.y = *reinterpret_cast<unsigned int*>(&o23);
    reinterpret_cast<uint2*>(g_Yh)[(size_t)n * D4 + lane] = p;
}

// ---------------------------------------------------------------------------
// Hop 2 fused with selection gather: one warp per OUTPUT row, fp16 gathers,
// fp32 accumulate, fp32 output (streaming store — out is never re-read).
// ---------------------------------------------------------------------------
__global__ void __launch_bounds__(256) hop2_direct_kernel(
    const int* __restrict__ sel,
    float4* __restrict__ out4)
{
    int row  = (blockIdx.x * blockDim.x + threadIdx.x) >> 5;
    int lane = threadIdx.x & 31;
    if (row >= N_POOL) return;

    int n = __ldg(sel + row);
    const uint2* yh2 = reinterpret_cast<const uint2*>(g_Yh);

    // residual from fp16 Y row
    uint2 r = __ldg(&yh2[(size_t)n * D4 + lane]);
    __half2 r01 = *reinterpret_cast<__half2*>(&r.x);
    __half2 r23 = *reinterpret_cast<__half2*>(&r.y);
    float2 q01 = __half22float2(r01);
    float2 q23 = __half22float2(r23);
    float4 acc = make_float4(q01.x, q01.y, q23.x, q23.y);

    int s0 = __ldg(&g_off[n])     + __ldg(&g_bsum[n >> 10]);
    int e0 = __ldg(&g_off[n + 1]) + __ldg(&g_bsum[(n + 1) >> 10]);

    #pragma unroll 4
    for (int j = s0; j < e0; ++j) {
        int2 e = __ldg(&g_epack[j]);               // uniform broadcast
        float w = __int_as_float(e.y);
        uint2 h = __ldg(&yh2[(size_t)(unsigned)e.x + lane]);
        __half2 h01 = *reinterpret_cast<__half2*>(&h.x);
        __half2 h23 = *reinterpret_cast<__half2*>(&h.y);
        float2 f01 = __half22float2(h01);
        float2 f23 = __half22float2(h23);
        acc.x += f01.x * w;
        acc.y += f01.y * w;
        acc.z += f23.x * w;
        acc.w += f23.y * w;
    }
    __stcs(&out4[(size_t)row * D4 + lane], acc);   // streaming store
}

// ---------------------------------------------------------------------------
extern "C" void kernel_launch(void* const* d_in, const int* in_sizes, int n_in,
                              void* d_out, int out_size)
{
    const float* x    = (const float*)d_in[0];   // [N, 128] f32
    const float* ea   = (const float*)d_in[1];   // [E] f32
    const int*   eidx = (const int*)d_in[2];     // [2, E] int32
    const int*   sel  = (const int*)d_in[3];     // [N_pool] int32
    float* out = (float*)d_out;

    const int* src = eidx;            // row 0 (x_j sources)
    const int* dst = eidx + N_EDGES;  // row 1 (aggregation targets)

    const float4* x4 = reinterpret_cast<const float4*>(x);
    const int TB = 256;

    // CSR build: (hist+rank|convert) -> fused scan -> atomic-free reorder
    hist_convert_kernel<<<(N4 + TB - 1) / TB, TB>>>(
        reinterpret_cast<const int4*>(dst), x4);
    scan_fused_kernel<<<NBLK, SCAN_B>>>();
    reorder_kernel<<<(N_EDGES / 2 + TB - 1) / TB, TB>>>(
        reinterpret_cast<const int2*>(src),
        reinterpret_cast<const int2*>(dst),
        reinterpret_cast<const float2*>(ea));

    // hop 1 (all nodes, fp16 gather, fp16 residual, fp16 out)
    hop1_kernel<<<(N_NODES * 32 + TB - 1) / TB, TB>>>();

    // hop 2 fused with output gather: out[i] = (Yh + A@Yh)[sel[i]]
    hop2_direct_kernel<<<(N_POOL * 32 + TB - 1) / TB, TB>>>(
        sel, (float4*)out);
}